// round 11
// baseline (speedup 1.0000x reference)
#include <cuda_runtime.h>
#include <cuda_bf16.h>
#include <cstdint>

#define BB 64
#define NN 2048
#define DD 512
#define KK 64
#define KGC 80

// Scratch (device globals — no allocation allowed)
__device__ __align__(16) __nv_bfloat16 g_aThi[(size_t)BB * KK * NN]; // assignT hi [b][k][n'] (pair-permuted n)
__device__ __align__(16) __nv_bfloat16 g_aTlo[(size_t)BB * KK * NN]; // assignT lo
__device__ float g_vpart[2][(size_t)BB * KK * DD];
__device__ float g_asum[BB * KK];
__device__ float g_norm2[BB * KK];
__device__ __align__(16) __nv_bfloat16 g_cHi[DD * KGC];
__device__ __align__(16) __nv_bfloat16 g_cLo[DD * KGC];
__device__ float g_c2T[KK * DD];

// ===================== helpers =====================
__device__ __forceinline__ uint32_t smem_to_u32(const void* p) {
    uint32_t a;
    asm("{ .reg .u64 t; cvta.to.shared.u64 t, %1; cvt.u32.u64 %0, t; }" : "=r"(a) : "l"(p));
    return a;
}
__device__ __forceinline__ void mma_bf16(float* c, const uint32_t* a, const uint32_t* b) {
    asm volatile("mma.sync.aligned.m16n8k16.row.col.f32.bf16.bf16.f32 "
        "{%0,%1,%2,%3}, {%4,%5,%6,%7}, {%8,%9}, {%0,%1,%2,%3};"
        : "+f"(c[0]), "+f"(c[1]), "+f"(c[2]), "+f"(c[3])
        : "r"(a[0]), "r"(a[1]), "r"(a[2]), "r"(a[3]), "r"(b[0]), "r"(b[1]));
}
__device__ __forceinline__ void ldsm_x4t(uint32_t* r, uint32_t addr) {
    asm volatile("ldmatrix.sync.aligned.m8n8.x4.trans.shared.b16 {%0,%1,%2,%3}, [%4];"
        : "=r"(r[0]), "=r"(r[1]), "=r"(r[2]), "=r"(r[3]) : "r"(addr));
}
__device__ __forceinline__ void ldsm_x2t(uint32_t* r, uint32_t addr) {
    asm volatile("ldmatrix.sync.aligned.m8n8.x2.trans.shared.b16 {%0,%1}, [%2];"
        : "=r"(r[0]), "=r"(r[1]) : "r"(addr));
}
__device__ __forceinline__ void split2(float2 v, uint32_t& hi, uint32_t& lo) {
    __nv_bfloat162 h = __float22bfloat162_rn(v);
    float2 hf = __bfloat1622float2(h);
    __nv_bfloat162 l = __float22bfloat162_rn(make_float2(v.x - hf.x, v.y - hf.y));
    hi = *(uint32_t*)&h;
    lo = *(uint32_t*)&l;
}
#define CP_ASYNC16(dst, src) \
    asm volatile("cp.async.cg.shared.global [%0], [%1], 16;" :: "r"(dst), "l"(src) : "memory")
#define CP_COMMIT() asm volatile("cp.async.commit_group;" ::: "memory")
#define CP_WAIT1()  asm volatile("cp.async.wait_group 1;" ::: "memory")

// ---------------------------------------------------------------------------
// Kernel P1: split clusters to bf16 hi/lo + zero accumulators
// ---------------------------------------------------------------------------
__global__ void k_prep(const float* __restrict__ clusters) {
    int i = blockIdx.x * 256 + threadIdx.x;
    if (i < DD * KGC) {
        float v = clusters[i];
        __nv_bfloat16 h = __float2bfloat16(v);
        g_cHi[i] = h;
        g_cLo[i] = __float2bfloat16(v - __bfloat162float(h));
    }
    if (i < BB * KK) { g_asum[i] = 0.0f; g_norm2[i] = 0.0f; }
}
// Kernel P2: transpose clusters2 [512][64] -> [64][512]
__global__ void k_prep2(const float* __restrict__ clusters2) {
    int k = blockIdx.x;
    int d = threadIdx.x;
    g_c2T[k * DD + d] = clusters2[d * KK + k];
}

// ---------------------------------------------------------------------------
// Kernel 1: logits GEMM (bf16x3 mma.sync, A fragments via direct LDG,
// B via cp.async triple-buffer) + BN + softmax + a_sum + assignT (permuted n)
// CTA: 256 threads, 4 M-warps x 2 N-warps, tile 128 x 80, 16 stages of 32 d.
// ---------------------------------------------------------------------------
// smem: 3 B-buffers of 11264 B (hi [32][88] @0, lo @5632), then epilogue scratch
#define L3_SZ 11264
#define L_BN  33792      // 240 floats
#define L_AS  34752      // 256 floats
#define L_PM  35776      // 256 floats
#define L_PS  36800      // 256 floats
#define L_SMEM 37824

__global__ __launch_bounds__(256, 2) void k_logits_mma(
    const float* __restrict__ x,
    const float* __restrict__ bnw, const float* __restrict__ bnb,
    const float* __restrict__ rm, const float* __restrict__ rv)
{
    extern __shared__ __align__(16) char smem[];
    const int tid = threadIdx.x;
    const int lane = tid & 31, w = tid >> 5;
    const int wm = w & 3, wn = w >> 2;
    const int gid = lane >> 2, q = lane & 3;
    const int b = blockIdx.y, n0 = blockIdx.x * 128;
    const float* xb = x + ((size_t)b * NN + n0) * DD;
    uint32_t sb32 = smem_to_u32(smem);

    float* sScale = (float*)(smem + L_BN);
    float* sRm = sScale + 80;
    float* sBb = sScale + 160;
    if (tid < KGC) {
        sScale[tid] = bnw[tid] * rsqrtf(rv[tid] + 1e-5f);
        sRm[tid] = rm[tid];
        sBb[tid] = bnb[tid];
    }

    float acc[2][5][4];
    #pragma unroll
    for (int mt = 0; mt < 2; mt++)
        #pragma unroll
        for (int nt = 0; nt < 5; nt++)
            #pragma unroll
            for (int e = 0; e < 4; e++) acc[mt][nt][e] = 0.f;

    // B cp.async mapping: 640 16B units (hi 320 + lo 320)
    const int bu0 = tid;               // unit 0..255
    const int bu1 = tid + 256;         // 256..511
    const int bu2 = tid + 512;         // 512..639 (tid<128)
    auto cp_b = [&](int stage, int unit) {
        int arr = unit >= 320;
        int u = arr ? unit - 320 : unit;
        int r = u / 10, c = u - r * 10;
        const __nv_bfloat16* src = (arr ? g_cLo : g_cHi) + (size_t)(stage * 32 + r) * KGC + c * 8;
        uint32_t dst = sb32 + (stage % 3) * L3_SZ + arr * 5632 + r * 176 + c * 16;
        CP_ASYNC16(dst, src);
    };

    // A fragment prefetch (float2 per fragment reg)
    float2 af[2][2][4];
    auto ldA = [&](int dtn) {
        #pragma unroll
        for (int kt = 0; kt < 2; kt++)
            #pragma unroll
            for (int mt = 0; mt < 2; mt++)
                #pragma unroll
                for (int i = 0; i < 4; i++)
                    af[kt][mt][i] = *(const float2*)&xb[
                        (size_t)(wm * 32 + mt * 16 + gid + (i & 1) * 8) * DD +
                        dtn * 32 + kt * 16 + q * 2 + (i >> 1) * 8];
    };

    // prologue: B(0) in flight, A(0) in regs
    cp_b(0, bu0); cp_b(0, bu1); if (tid < 128) cp_b(0, bu2);
    CP_COMMIT();
    ldA(0);

    uint32_t ah[2][2][4], al[2][2][4];

    for (int dt = 0; dt < 16; dt++) {
        // convert this stage's A fragments
        #pragma unroll
        for (int kt = 0; kt < 2; kt++)
            #pragma unroll
            for (int mt = 0; mt < 2; mt++)
                #pragma unroll
                for (int i = 0; i < 4; i++)
                    split2(af[kt][mt][i], ah[kt][mt][i], al[kt][mt][i]);
        // prefetch next stage
        if (dt < 15) {
            cp_b(dt + 1, bu0); cp_b(dt + 1, bu1); if (tid < 128) cp_b(dt + 1, bu2);
            CP_COMMIT();
            ldA(dt + 1);
            CP_WAIT1();          // B(dt) complete, B(dt+1) may fly
        } else {
            asm volatile("cp.async.wait_group 0;" ::: "memory");
        }
        __syncthreads();

        uint32_t bufo = sb32 + (uint32_t)((dt % 3) * L3_SZ);
        #pragma unroll
        for (int kt = 0; kt < 2; kt++) {
            uint32_t bh[5][2], bl[5][2];
            #pragma unroll
            for (int p = 0; p < 2; p++) {
                uint32_t t[4];
                uint32_t boff = (uint32_t)((kt * 16 + (lane & 15)) * 176 +
                                           (wn * 40 + p * 16 + (lane >> 4) * 8) * 2);
                ldsm_x4t(t, bufo + boff);
                bh[2*p][0] = t[0]; bh[2*p][1] = t[1];
                bh[2*p+1][0] = t[2]; bh[2*p+1][1] = t[3];
                ldsm_x4t(t, bufo + 5632 + boff);
                bl[2*p][0] = t[0]; bl[2*p][1] = t[1];
                bl[2*p+1][0] = t[2]; bl[2*p+1][1] = t[3];
            }
            {
                uint32_t boff = (uint32_t)((kt * 16 + (lane & 15)) * 176 + (wn * 40 + 32) * 2);
                ldsm_x2t(bh[4], bufo + boff);
                ldsm_x2t(bl[4], bufo + 5632 + boff);
            }
            #pragma unroll
            for (int nt = 0; nt < 5; nt++)
                #pragma unroll
                for (int mt = 0; mt < 2; mt++) {
                    mma_bf16(acc[mt][nt], ah[kt][mt], bh[nt]);
                    mma_bf16(acc[mt][nt], ah[kt][mt], bl[nt]);
                    mma_bf16(acc[mt][nt], al[kt][mt], bh[nt]);
                }
        }
        if (dt < 15) __syncthreads();   // protect buf[(dt+1)%3] writer (cp.async next iter)
    }
    __syncthreads();

    // ---- BN affine ----
    #pragma unroll
    for (int nt = 0; nt < 5; nt++) {
        int c0 = wn * 40 + nt * 8 + q * 2;
        float s0 = sScale[c0], s1 = sScale[c0 + 1];
        float m0 = sRm[c0],    m1 = sRm[c0 + 1];
        float q0 = sBb[c0],    q1 = sBb[c0 + 1];
        #pragma unroll
        for (int mt = 0; mt < 2; mt++) {
            acc[mt][nt][0] = (acc[mt][nt][0] - m0) * s0 + q0;
            acc[mt][nt][1] = (acc[mt][nt][1] - m1) * s1 + q1;
            acc[mt][nt][2] = (acc[mt][nt][2] - m0) * s0 + q0;
            acc[mt][nt][3] = (acc[mt][nt][3] - m1) * s1 + q1;
        }
    }

    // ---- softmax: rows split across 2 N-warps -> 2-pass smem reduction ----
    float* sPM = (float*)(smem + L_PM);
    float* sPS = (float*)(smem + L_PS);
    float* sOut = (float*)smem;                  // [128][66] floats = 33792 B

    #pragma unroll
    for (int h = 0; h < 4; h++) {
        int mt = h >> 1, hh = h & 1;
        float mx = -3.4e38f;
        #pragma unroll
        for (int nt = 0; nt < 5; nt++)
            mx = fmaxf(mx, fmaxf(acc[mt][nt][hh * 2], acc[mt][nt][hh * 2 + 1]));
        mx = fmaxf(mx, __shfl_xor_sync(0xffffffffu, mx, 1));
        mx = fmaxf(mx, __shfl_xor_sync(0xffffffffu, mx, 2));
        int row = wm * 32 + mt * 16 + hh * 8 + gid;
        if (q == 0) sPM[row * 2 + wn] = mx;
    }
    __syncthreads();
    #pragma unroll
    for (int h = 0; h < 4; h++) {
        int mt = h >> 1, hh = h & 1;
        int row = wm * 32 + mt * 16 + hh * 8 + gid;
        float m = fmaxf(sPM[row * 2], sPM[row * 2 + 1]);
        float sum = 0.f;
        #pragma unroll
        for (int nt = 0; nt < 5; nt++) {
            float e0 = __expf(acc[mt][nt][hh * 2] - m);
            float e1 = __expf(acc[mt][nt][hh * 2 + 1] - m);
            acc[mt][nt][hh * 2] = e0;
            acc[mt][nt][hh * 2 + 1] = e1;
            sum += e0 + e1;
        }
        sum += __shfl_xor_sync(0xffffffffu, sum, 1);
        sum += __shfl_xor_sync(0xffffffffu, sum, 2);
        if (q == 0) sPS[row * 2 + wn] = sum;
    }
    __syncthreads();
    const int ntmax = wn ? 3 : 5;
    #pragma unroll
    for (int h = 0; h < 4; h++) {
        int mt = h >> 1, hh = h & 1;
        int row = wm * 32 + mt * 16 + hh * 8 + gid;
        float inv = 1.0f / (sPS[row * 2] + sPS[row * 2 + 1]);
        #pragma unroll
        for (int nt = 0; nt < 5; nt++) {
            if (nt < ntmax) {
                int col = wn * 40 + nt * 8 + q * 2;
                float2 v = make_float2(acc[mt][nt][hh * 2] * inv,
                                       acc[mt][nt][hh * 2 + 1] * inv);
                *(float2*)&sOut[row * 66 + col] = v;
            }
        }
    }
    __syncthreads();

    // ---- a_sum ----
    float* sAs = (float*)(smem + L_AS);
    {
        int k = tid & 63, qq = tid >> 6;
        float s = 0.f;
        #pragma unroll 8
        for (int r = qq * 32; r < qq * 32 + 32; r++) s += sOut[r * 66 + k];
        sAs[qq * 64 + k] = s;
    }
    __syncthreads();
    if (tid < KK)
        atomicAdd(&g_asum[b * KK + tid],
                  sAs[tid] + sAs[64 + tid] + sAs[128 + tid] + sAs[192 + tid]);

    // ---- assignT bf16 hi/lo with pair-permuted n (fragment-friendly) ----
    {
        int row = tid & 127, kh = (tid >> 7) * 32;
        int p = (row >> 1) & 7;
        int slot = (p & 3) * 2 + (p >> 2);
        int rowp = (row & ~15) | (slot * 2 + (row & 1));
        __nv_bfloat16* aThi = g_aThi + (size_t)b * KK * NN + n0 + rowp;
        __nv_bfloat16* aTlo = g_aTlo + (size_t)b * KK * NN + n0 + rowp;
        #pragma unroll 4
        for (int kk2 = 0; kk2 < 32; kk2++) {
            int k = kh + kk2;
            float v = sOut[row * 66 + k];
            __nv_bfloat16 h = __float2bfloat16(v);
            aThi[(size_t)k * NN] = h;
            aTlo[(size_t)k * NN] = __float2bfloat16(v - __bfloat162float(h));
        }
    }
}

// ---------------------------------------------------------------------------
// Kernel 2: vlad GEMM: D[k][d] = assignT @ x. A (aT) fragments via direct
// LDG.64 from permuted layout; x (B) double-buffered smem. 2 n-chunks.
// ---------------------------------------------------------------------------
#define VB_SZ 17408      // XH [32][272] @0, XL @8704

__global__ __launch_bounds__(256, 2) void k_vlad_mma(const float* __restrict__ x)
{
    __shared__ __align__(16) char sm[2 * VB_SZ];
    const int tid = threadIdx.x, lane = tid & 31, w = tid >> 5;
    const int wm = w & 1, wn = w >> 1;
    const int gid = lane >> 2, q = lane & 3;
    const int b = blockIdx.z, chunk = blockIdx.y, d0 = blockIdx.x * 128;
    const float* xb = x + (size_t)b * NN * DD + d0;
    const __nv_bfloat16* aThi = g_aThi + (size_t)b * KK * NN;
    const __nv_bfloat16* aTlo = g_aTlo + (size_t)b * KK * NN;
    uint32_t sb32 = smem_to_u32(sm);

    float acc[2][4][4];
    #pragma unroll
    for (int mt = 0; mt < 2; mt++)
        #pragma unroll
        for (int nt = 0; nt < 4; nt++)
            #pragma unroll
            for (int e = 0; e < 4; e++) acc[mt][nt][e] = 0.f;

    const int xr_r = tid >> 5, xr_u = tid & 31;
    float4 xr[4];
    {
        const int nbase = chunk * 1024;
        #pragma unroll
        for (int j = 0; j < 4; j++)
            xr[j] = *(const float4*)&xb[(size_t)(nbase + xr_r + j * 8) * DD + xr_u * 4];
    }

    for (int nc = 0; nc < 32; nc++) {
        const int nbase = chunk * 1024 + nc * 32;
        char* buf = sm + (nc & 1) * VB_SZ;
        // STS prefetched x tile
        #pragma unroll
        for (int j = 0; j < 4; j++) {
            uint32_t h0, l0, h1, l1;
            split2(make_float2(xr[j].x, xr[j].y), h0, l0);
            split2(make_float2(xr[j].z, xr[j].w), h1, l1);
            int off = (xr_r + j * 8) * 272 + xr_u * 8;
            *(uint2*)(buf + off) = make_uint2(h0, h1);
            *(uint2*)(buf + 8704 + off) = make_uint2(l0, l1);
        }
        // prefetch next x tile
        if (nc < 31) {
            #pragma unroll
            for (int j = 0; j < 4; j++)
                xr[j] = *(const float4*)&xb[(size_t)(nbase + 32 + xr_r + j * 8) * DD + xr_u * 4];
        }
        __syncthreads();

        // aT fragments: direct LDG.64 (permuted layout). reg map:
        // h0.x=r0(row,q2pair) h1.x=r1(row+8) h0.y=r2(row,q2+8pair) h1.y=r3
        uint32_t ahv[2][2][4], alv[2][2][4];
        #pragma unroll
        for (int kt = 0; kt < 2; kt++)
            #pragma unroll
            for (int mt = 0; mt < 2; mt++) {
                int krow = wm * 32 + mt * 16 + gid;
                size_t e0 = (size_t)krow * NN + nbase + kt * 16 + q * 4;
                size_t e1 = (size_t)(krow + 8) * NN + nbase + kt * 16 + q * 4;
                uint2 h0 = *(const uint2*)(aThi + e0);
                uint2 h1 = *(const uint2*)(aThi + e1);
                uint2 l0 = *(const uint2*)(aTlo + e0);
                uint2 l1 = *(const uint2*)(aTlo + e1);
                ahv[kt][mt][0] = h0.x; ahv[kt][mt][1] = h1.x;
                ahv[kt][mt][2] = h0.y; ahv[kt][mt][3] = h1.y;
                alv[kt][mt][0] = l0.x; alv[kt][mt][1] = l1.x;
                alv[kt][mt][2] = l0.y; alv[kt][mt][3] = l1.y;
            }

        uint32_t bufo = sb32 + (uint32_t)((nc & 1) * VB_SZ);
        #pragma unroll
        for (int kt = 0; kt < 2; kt++) {
            uint32_t bh[4][2], bl[4][2];
            #pragma unroll
            for (int p = 0; p < 2; p++) {
                uint32_t t[4];
                uint32_t boff = (uint32_t)((kt * 16 + (lane & 15)) * 272 +
                                           (wn * 32 + p * 16 + (lane >> 4) * 8) * 2);
                ldsm_x4t(t, bufo + boff);
                bh[2*p][0] = t[0]; bh[2*p][1] = t[1];
                bh[2*p+1][0] = t[2]; bh[2*p+1][1] = t[3];
                ldsm_x4t(t, bufo + 8704 + boff);
                bl[2*p][0] = t[0]; bl[2*p][1] = t[1];
                bl[2*p+1][0] = t[2]; bl[2*p+1][1] = t[3];
            }
            #pragma unroll
            for (int nt = 0; nt < 4; nt++)
                #pragma unroll
                for (int mt = 0; mt < 2; mt++) {
                    mma_bf16(acc[mt][nt], ahv[kt][mt], bh[nt]);
                    mma_bf16(acc[mt][nt], ahv[kt][mt], bl[nt]);
                    mma_bf16(acc[mt][nt], alv[kt][mt], bh[nt]);
                }
        }
        __syncthreads();
    }

    float* vp = g_vpart[chunk] + (size_t)b * KK * DD;
    #pragma unroll
    for (int mt = 0; mt < 2; mt++) {
        int k0 = wm * 32 + mt * 16 + gid;
        #pragma unroll
        for (int nt = 0; nt < 4; nt++) {
            int d = d0 + wn * 32 + nt * 8 + q * 2;
            *(float2*)&vp[(size_t)k0 * DD + d]       = make_float2(acc[mt][nt][0], acc[mt][nt][1]);
            *(float2*)&vp[(size_t)(k0 + 8) * DD + d] = make_float2(acc[mt][nt][2], acc[mt][nt][3]);
        }
    }
}

// ---------------------------------------------------------------------------
// Kernel 3: finisher — sum partials, subtract a_sum*clusters2, transpose to
// out[b][d][k], per-(b,k) norm^2.
// ---------------------------------------------------------------------------
__global__ __launch_bounds__(256) void k_fin(float* __restrict__ out)
{
    __shared__ float sT[64][66];
    __shared__ float sN[64];
    const int b = blockIdx.y, dg = blockIdx.x;
    const int lane = threadIdx.x & 31, w = threadIdx.x >> 5;
    const float* vp0 = g_vpart[0] + (size_t)b * KK * DD;
    const float* vp1 = g_vpart[1] + (size_t)b * KK * DD;

    #pragma unroll
    for (int kr = 0; kr < 8; kr++) {
        int k = w * 8 + kr;
        float as = g_asum[b * KK + k];
        int d = dg * 64 + lane;
        float v0 = vp0[(size_t)k * DD + d]      + vp1[(size_t)k * DD + d]
                 - as * g_c2T[k * DD + d];
        float v1 = vp0[(size_t)k * DD + d + 32] + vp1[(size_t)k * DD + d + 32]
                 - as * g_c2T[k * DD + d + 32];
        sT[lane][k]      = v0;
        sT[lane + 32][k] = v1;
        float n2 = v0 * v0 + v1 * v1;
        #pragma unroll
        for (int o = 16; o >= 1; o >>= 1) n2 += __shfl_xor_sync(0xffffffffu, n2, o);
        if (lane == 0) sN[k] = n2;
    }
    __syncthreads();
    if (threadIdx.x < KK)
        atomicAdd(&g_norm2[b * KK + threadIdx.x], sN[threadIdx.x]);
    #pragma unroll
    for (int j = 0; j < 16; j++) {
        int idx = threadIdx.x + j * 256;
        int d = idx >> 6, k = idx & 63;
        out[((size_t)b * DD + dg * 64 + d) * KK + k] = sT[d][k];
    }
}

// ---------------------------------------------------------------------------
// Kernel 4: fused scale compute + in-place output scaling
// ---------------------------------------------------------------------------
__global__ __launch_bounds__(256) void k_out(float* __restrict__ out) {
    __shared__ float sInv[KK];
    __shared__ float sh[2];
    const int b = blockIdx.y, dg = blockIdx.x;
    const int t = threadIdx.x;
    if (t < KK) {
        float n2 = g_norm2[b * KK + t];
        float inv = 1.0f / fmaxf(sqrtf(n2), 1e-12f);
        float c = n2 * inv * inv;
        #pragma unroll
        for (int o = 16; o >= 1; o >>= 1) c += __shfl_xor_sync(0xffffffffu, c, o);
        if ((t & 31) == 0) sh[t >> 5] = c;
        sInv[t] = inv;
    }
    __syncthreads();
    float invt = 1.0f / fmaxf(sqrtf(sh[0] + sh[1]), 1e-12f);
    size_t base = (size_t)b * DD * KK + (size_t)dg * 4096;
    #pragma unroll
    for (int j = 0; j < 16; j++) {
        int i = t + j * 256;
        out[base + i] = out[base + i] * (sInv[i & 63] * invt);
    }
}

// ---------------------------------------------------------------------------
extern "C" void kernel_launch(void* const* d_in, const int* in_sizes, int n_in,
                              void* d_out, int out_size) {
    const float* x         = (const float*)d_in[0];
    const float* clusters  = (const float*)d_in[1];
    const float* clusters2 = (const float*)d_in[2];
    const float* bnw       = (const float*)d_in[3];
    const float* bnb       = (const float*)d_in[4];
    const float* rm        = (const float*)d_in[5];
    const float* rv        = (const float*)d_in[6];
    float* out = (float*)d_out;

    cudaFuncSetAttribute(k_logits_mma, cudaFuncAttributeMaxDynamicSharedMemorySize, L_SMEM);

    k_prep<<<(DD * KGC + 255) / 256, 256>>>(clusters);
    k_prep2<<<KK, DD>>>(clusters2);
    dim3 g1(NN / 128, BB);
    k_logits_mma<<<g1, 256, L_SMEM>>>(x, bnw, bnb, rm, rv);
    dim3 g2(DD / 128, 2, BB);
    k_vlad_mma<<<g2, 256>>>(x);
    dim3 g3(8, BB);
    k_fin<<<g3, 256>>>(out);
    dim3 g4(8, BB);
    k_out<<<g4, 256>>>(out);
}

// round 12
// speedup vs baseline: 1.5350x; 1.5350x over previous
#include <cuda_runtime.h>
#include <cuda_bf16.h>
#include <cstdint>

#define BB 64
#define NN 2048
#define DD 512
#define KK 64
#define KGC 80

// Scratch (device globals — no allocation allowed)
__device__ __align__(16) __nv_bfloat16 g_aThi[(size_t)BB * KK * NN]; // assignT hi [b][k][n]
__device__ __align__(16) __nv_bfloat16 g_aTlo[(size_t)BB * KK * NN]; // assignT lo
__device__ float g_vpart[2][(size_t)BB * KK * DD];
__device__ float g_asum[BB * KK];
__device__ float g_norm2[BB * KK];
__device__ __align__(16) __nv_bfloat16 g_cHi[DD * KGC];
__device__ __align__(16) __nv_bfloat16 g_cLo[DD * KGC];
__device__ float g_c2T[KK * DD];

// ===================== helpers =====================
__device__ __forceinline__ uint32_t smem_to_u32(const void* p) {
    uint32_t a;
    asm("{ .reg .u64 t; cvta.to.shared.u64 t, %1; cvt.u32.u64 %0, t; }" : "=r"(a) : "l"(p));
    return a;
}
__device__ __forceinline__ void mma_bf16(float* c, const uint32_t* a, const uint32_t* b) {
    asm volatile("mma.sync.aligned.m16n8k16.row.col.f32.bf16.bf16.f32 "
        "{%0,%1,%2,%3}, {%4,%5,%6,%7}, {%8,%9}, {%0,%1,%2,%3};"
        : "+f"(c[0]), "+f"(c[1]), "+f"(c[2]), "+f"(c[3])
        : "r"(a[0]), "r"(a[1]), "r"(a[2]), "r"(a[3]), "r"(b[0]), "r"(b[1]));
}
__device__ __forceinline__ void ldsm_x4(uint32_t* r, uint32_t addr) {
    asm volatile("ldmatrix.sync.aligned.m8n8.x4.shared.b16 {%0,%1,%2,%3}, [%4];"
        : "=r"(r[0]), "=r"(r[1]), "=r"(r[2]), "=r"(r[3]) : "r"(addr));
}
__device__ __forceinline__ void ldsm_x4t(uint32_t* r, uint32_t addr) {
    asm volatile("ldmatrix.sync.aligned.m8n8.x4.trans.shared.b16 {%0,%1,%2,%3}, [%4];"
        : "=r"(r[0]), "=r"(r[1]), "=r"(r[2]), "=r"(r[3]) : "r"(addr));
}
__device__ __forceinline__ void ldsm_x2t(uint32_t* r, uint32_t addr) {
    asm volatile("ldmatrix.sync.aligned.m8n8.x2.trans.shared.b16 {%0,%1}, [%2];"
        : "=r"(r[0]), "=r"(r[1]) : "r"(addr));
}
__device__ __forceinline__ void split2(float2 v, uint32_t& hi, uint32_t& lo) {
    __nv_bfloat162 h = __float22bfloat162_rn(v);
    float2 hf = __bfloat1622float2(h);
    __nv_bfloat162 l = __float22bfloat162_rn(make_float2(v.x - hf.x, v.y - hf.y));
    hi = *(uint32_t*)&h;
    lo = *(uint32_t*)&l;
}
#define CP_ASYNC16(dst, src) \
    asm volatile("cp.async.cg.shared.global [%0], [%1], 16;" :: "r"(dst), "l"(src) : "memory")
#define CP_COMMIT() asm volatile("cp.async.commit_group;" ::: "memory")
#define CP_WAIT0()  asm volatile("cp.async.wait_group 0;" ::: "memory")

// ---------------------------------------------------------------------------
// Kernel P1: split clusters to bf16 hi/lo + zero accumulators
// ---------------------------------------------------------------------------
__global__ void k_prep(const float* __restrict__ clusters) {
    int i = blockIdx.x * 256 + threadIdx.x;
    if (i < DD * KGC) {
        float v = clusters[i];
        __nv_bfloat16 h = __float2bfloat16(v);
        g_cHi[i] = h;
        g_cLo[i] = __float2bfloat16(v - __bfloat162float(h));
    }
    if (i < BB * KK) { g_asum[i] = 0.0f; g_norm2[i] = 0.0f; }
}
// Kernel P2: transpose clusters2 [512][64] -> [64][512]
__global__ void k_prep2(const float* __restrict__ clusters2) {
    int k = blockIdx.x;
    int d = threadIdx.x;
    g_c2T[k * DD + d] = clusters2[d * KK + k];
}

// ---------------------------------------------------------------------------
// Kernel 1: logits GEMM (mma.sync bf16x3) + BN + softmax + a_sum + assignT
// CTA: 256 threads = 8 warps, 4 M-split x 2 N-split. Tile M=128 x N=80,
// K=512 in 16 chunks of 32 d, double-buffered smem, 1 sync/stage.
// A: register prefetch + convert + STS (stride 80, 16-aligned).
// B: cp.async.cg direct global->smem (bf16 pre-split).
// ---------------------------------------------------------------------------
// per-buffer (31744 B): AH [128][40]bf16(80B) @0, AL @10240,
//                       BH [32][88]bf16(176B) @20480, BL @26112
#define LB_AH 0
#define LB_AL 10240
#define LB_BH 20480
#define LB_BL 26112
#define LB_SZ 31744
#define L_BN  63488      // 240 floats
#define L_AS  64448      // 256 floats
#define L_PM  65472      // 256 floats
#define L_PS  66496      // 256 floats
#define L_SMEM 67520

__global__ __launch_bounds__(256, 2) void k_logits_mma(
    const float* __restrict__ x,
    const float* __restrict__ bnw, const float* __restrict__ bnb,
    const float* __restrict__ rm, const float* __restrict__ rv)
{
    extern __shared__ __align__(16) char smem[];
    const int tid = threadIdx.x;
    const int lane = tid & 31, w = tid >> 5;
    const int wm = w & 3, wn = w >> 2;           // 4 M-warps x 2 N-warps
    const int b = blockIdx.y, n0 = blockIdx.x * 128;
    const float* xb = x + ((size_t)b * NN + n0) * DD;
    uint32_t sb32 = smem_to_u32(smem);

    float* sScale = (float*)(smem + L_BN);
    float* sRm = sScale + 80;
    float* sBb = sScale + 160;
    if (tid < KGC) {
        sScale[tid] = bnw[tid] * rsqrtf(rv[tid] + 1e-5f);
        sRm[tid] = rm[tid];
        sBb[tid] = bnb[tid];
    }

    float acc[2][5][4];
    #pragma unroll
    for (int mt = 0; mt < 2; mt++)
        #pragma unroll
        for (int nt = 0; nt < 5; nt++)
            #pragma unroll
            for (int e = 0; e < 4; e++) acc[mt][nt][e] = 0.f;

    // A prefetch lanes: x rows xr_r + j*32 (j=0..3), 8 float4 per 32-d row
    const int xr_r = tid >> 3, xr_u = tid & 7;
    // B cp.async: 640 16B units per stage (hi 320 + lo 320)
    const int br0 = tid / 10, bc0 = tid - br0 * 10;            // unit tid (<256, hi)
    const int bidx1 = tid + 256;
    const int u1 = bidx1 >= 320 ? bidx1 - 320 : bidx1;         // hi tail or lo head
    const int barr1 = bidx1 >= 320;
    const int br1 = u1 / 10, bc1 = u1 - br1 * 10;
    const int bidx2 = tid + 512;                                // lo (tid<128)
    const int u2 = bidx2 - 320;
    const int br2 = u2 / 10, bc2 = u2 - br2 * 10;
    const bool bp2 = tid < 128;

    auto cp_b = [&](int stage) {
        uint32_t base = sb32 + (uint32_t)((stage & 1) * LB_SZ);
        const __nv_bfloat16* s0 = g_cHi + (size_t)(stage * 32 + br0) * KGC + bc0 * 8;
        CP_ASYNC16(base + LB_BH + br0 * 176 + bc0 * 16, s0);
        const __nv_bfloat16* s1 = (barr1 ? g_cLo : g_cHi) + (size_t)(stage * 32 + br1) * KGC + bc1 * 8;
        CP_ASYNC16(base + (barr1 ? LB_BL : LB_BH) + br1 * 176 + bc1 * 16, s1);
        if (bp2) {
            const __nv_bfloat16* s2 = g_cLo + (size_t)(stage * 32 + br2) * KGC + bc2 * 8;
            CP_ASYNC16(base + LB_BL + br2 * 176 + bc2 * 16, s2);
        }
        CP_COMMIT();
    };

    float4 xr[4];
    // ---- prologue: B(0) in flight, A(0) in regs ----
    cp_b(0);
    #pragma unroll
    for (int j = 0; j < 4; j++)
        xr[j] = *(const float4*)&xb[(size_t)(xr_r + j * 32) * DD + xr_u * 4];

    for (int dt = 0; dt < 16; dt++) {
        char* buf = smem + (dt & 1) * LB_SZ;
        // ---- STS prefetched x (convert) ----
        #pragma unroll
        for (int j = 0; j < 4; j++) {
            uint32_t h0, l0, h1, l1;
            split2(make_float2(xr[j].x, xr[j].y), h0, l0);
            split2(make_float2(xr[j].z, xr[j].w), h1, l1);
            int off = (xr_r + j * 32) * 80 + xr_u * 8;
            *(uint2*)(buf + LB_AH + off) = make_uint2(h0, h1);
            *(uint2*)(buf + LB_AL + off) = make_uint2(l0, l1);
        }
        // ---- prefetch next A ----
        if (dt < 15) {
            #pragma unroll
            for (int j = 0; j < 4; j++)
                xr[j] = *(const float4*)&xb[(size_t)(xr_r + j * 32) * DD +
                                            (dt + 1) * 32 + xr_u * 4];
        }
        CP_WAIT0();                 // B(dt) landed
        __syncthreads();
        if (dt < 15) cp_b(dt + 1);  // safe: MMA(dt-1) on that buffer done pre-sync

        uint32_t bufo = sb32 + (uint32_t)((dt & 1) * LB_SZ);
        #pragma unroll
        for (int kt = 0; kt < 2; kt++) {
            uint32_t ah[2][4], al[2][4];
            #pragma unroll
            for (int mt = 0; mt < 2; mt++) {
                uint32_t aoff = (uint32_t)((wm * 32 + mt * 16 + (lane & 15)) * 80 +
                                           (kt * 16 + (lane >> 4) * 8) * 2);
                ldsm_x4(ah[mt], bufo + LB_AH + aoff);
                ldsm_x4(al[mt], bufo + LB_AL + aoff);
            }
            uint32_t bh[5][2], bl[5][2];
            #pragma unroll
            for (int p = 0; p < 2; p++) {
                uint32_t t[4];
                uint32_t boff = (uint32_t)((kt * 16 + (lane & 15)) * 176 +
                                           (wn * 40 + p * 16 + (lane >> 4) * 8) * 2);
                ldsm_x4t(t, bufo + LB_BH + boff);
                bh[2*p][0] = t[0]; bh[2*p][1] = t[1];
                bh[2*p+1][0] = t[2]; bh[2*p+1][1] = t[3];
                ldsm_x4t(t, bufo + LB_BL + boff);
                bl[2*p][0] = t[0]; bl[2*p][1] = t[1];
                bl[2*p+1][0] = t[2]; bl[2*p+1][1] = t[3];
            }
            {
                uint32_t boff = (uint32_t)((kt * 16 + (lane & 15)) * 176 + (wn * 40 + 32) * 2);
                ldsm_x2t(bh[4], bufo + LB_BH + boff);
                ldsm_x2t(bl[4], bufo + LB_BL + boff);
            }
            #pragma unroll
            for (int nt = 0; nt < 5; nt++)
                #pragma unroll
                for (int mt = 0; mt < 2; mt++) {
                    mma_bf16(acc[mt][nt], ah[mt], bh[nt]);
                    mma_bf16(acc[mt][nt], ah[mt], bl[nt]);
                    mma_bf16(acc[mt][nt], al[mt], bh[nt]);
                }
        }
    }
    __syncthreads();

    // ---- BN affine ----
    #pragma unroll
    for (int nt = 0; nt < 5; nt++) {
        int c0 = wn * 40 + nt * 8 + (lane & 3) * 2;
        float s0 = sScale[c0], s1 = sScale[c0 + 1];
        float m0 = sRm[c0],    m1 = sRm[c0 + 1];
        float q0 = sBb[c0],    q1 = sBb[c0 + 1];
        #pragma unroll
        for (int mt = 0; mt < 2; mt++) {
            acc[mt][nt][0] = (acc[mt][nt][0] - m0) * s0 + q0;
            acc[mt][nt][1] = (acc[mt][nt][1] - m1) * s1 + q1;
            acc[mt][nt][2] = (acc[mt][nt][2] - m0) * s0 + q0;
            acc[mt][nt][3] = (acc[mt][nt][3] - m1) * s1 + q1;
        }
    }

    // ---- softmax: rows split across 2 N-warps -> 2-pass smem reduction ----
    float* sPM = (float*)(smem + L_PM);
    float* sPS = (float*)(smem + L_PS);
    float* sOut = (float*)smem;                  // [128][66] floats

    #pragma unroll
    for (int h = 0; h < 4; h++) {
        int mt = h >> 1, hh = h & 1;
        float mx = -3.4e38f;
        #pragma unroll
        for (int nt = 0; nt < 5; nt++)
            mx = fmaxf(mx, fmaxf(acc[mt][nt][hh * 2], acc[mt][nt][hh * 2 + 1]));
        mx = fmaxf(mx, __shfl_xor_sync(0xffffffffu, mx, 1));
        mx = fmaxf(mx, __shfl_xor_sync(0xffffffffu, mx, 2));
        int row = wm * 32 + mt * 16 + hh * 8 + (lane >> 2);
        if ((lane & 3) == 0) sPM[row * 2 + wn] = mx;
    }
    __syncthreads();
    #pragma unroll
    for (int h = 0; h < 4; h++) {
        int mt = h >> 1, hh = h & 1;
        int row = wm * 32 + mt * 16 + hh * 8 + (lane >> 2);
        float m = fmaxf(sPM[row * 2], sPM[row * 2 + 1]);
        float sum = 0.f;
        #pragma unroll
        for (int nt = 0; nt < 5; nt++) {
            float e0 = __expf(acc[mt][nt][hh * 2] - m);
            float e1 = __expf(acc[mt][nt][hh * 2 + 1] - m);
            acc[mt][nt][hh * 2] = e0;
            acc[mt][nt][hh * 2 + 1] = e1;
            sum += e0 + e1;
        }
        sum += __shfl_xor_sync(0xffffffffu, sum, 1);
        sum += __shfl_xor_sync(0xffffffffu, sum, 2);
        if ((lane & 3) == 0) sPS[row * 2 + wn] = sum;
    }
    __syncthreads();
    const int ntmax = wn ? 3 : 5;                // keep cols < 64 only
    #pragma unroll
    for (int h = 0; h < 4; h++) {
        int mt = h >> 1, hh = h & 1;
        int row = wm * 32 + mt * 16 + hh * 8 + (lane >> 2);
        float inv = 1.0f / (sPS[row * 2] + sPS[row * 2 + 1]);
        #pragma unroll
        for (int nt = 0; nt < 5; nt++) {
            if (nt < ntmax) {
                int col = wn * 40 + nt * 8 + (lane & 3) * 2;
                float2 v = make_float2(acc[mt][nt][hh * 2] * inv,
                                       acc[mt][nt][hh * 2 + 1] * inv);
                *(float2*)&sOut[row * 66 + col] = v;
            }
        }
    }
    __syncthreads();

    // ---- a_sum ----
    float* sAs = (float*)(smem + L_AS);
    {
        int k = tid & 63, qq = tid >> 6;
        float s = 0.f;
        #pragma unroll 8
        for (int r = qq * 32; r < qq * 32 + 32; r++) s += sOut[r * 66 + k];
        sAs[qq * 64 + k] = s;
    }
    __syncthreads();
    if (tid < KK)
        atomicAdd(&g_asum[b * KK + tid],
                  sAs[tid] + sAs[64 + tid] + sAs[128 + tid] + sAs[192 + tid]);

    // ---- assignment^T as bf16 hi/lo: coalesced in n ----
    {
        int row = tid & 127, kh = (tid >> 7) * 32;
        __nv_bfloat16* aThi = g_aThi + (size_t)b * KK * NN + n0 + row;
        __nv_bfloat16* aTlo = g_aTlo + (size_t)b * KK * NN + n0 + row;
        #pragma unroll 4
        for (int kk2 = 0; kk2 < 32; kk2++) {
            int k = kh + kk2;
            float v = sOut[row * 66 + k];
            __nv_bfloat16 h = __float2bfloat16(v);
            aThi[(size_t)k * NN] = h;
            aTlo[(size_t)k * NN] = __float2bfloat16(v - __bfloat162float(h));
        }
    }
}

// ---------------------------------------------------------------------------
// Kernel 2: vlad GEMM (mma.sync bf16x3): D[k_clu][d] = assign^T @ x
// CTA: 256 threads (2 M x 4 N warps), tile M=64 x N=128 d, K(n)=1024/chunk.
// x: register prefetch + convert + STS. aT: cp.async (bf16 pre-split).
// Double-buffered, 1 sync/stage.
// ---------------------------------------------------------------------------
// per-buffer (27648 B): XH [32][272] @0, XL @8704, ATH [64][40](80B) @17408,
//                       ATL @22528
#define VB_XH 0
#define VB_XL 8704
#define VB_AH 17408
#define VB_AL 22528
#define VB_SZ 27648

__global__ __launch_bounds__(256, 2) void k_vlad_mma(const float* __restrict__ x)
{
    __shared__ __align__(16) char sm[2 * VB_SZ];
    const int tid = threadIdx.x, lane = tid & 31, w = tid >> 5;
    const int wm = w & 1, wn = w >> 1;
    const int b = blockIdx.z, chunk = blockIdx.y, d0 = blockIdx.x * 128;
    const float* xb = x + (size_t)b * NN * DD + d0;
    const __nv_bfloat16* aThi = g_aThi + (size_t)b * KK * NN;
    const __nv_bfloat16* aTlo = g_aTlo + (size_t)b * KK * NN;
    uint32_t sb32 = smem_to_u32(sm);

    float acc[2][4][4];
    #pragma unroll
    for (int mt = 0; mt < 2; mt++)
        #pragma unroll
        for (int nt = 0; nt < 4; nt++)
            #pragma unroll
            for (int e = 0; e < 4; e++) acc[mt][nt][e] = 0.f;

    const int xr_r = tid >> 5, xr_u = tid & 31;  // x rows (8/iter), d-quad
    const int ar_r = tid >> 2, ar_u = tid & 3;   // aT row, n-unit

    auto cp_a = [&](int nc) {
        const int nbase = chunk * 1024 + nc * 32;
        uint32_t base = sb32 + (uint32_t)((nc & 1) * VB_SZ);
        size_t ge = (size_t)ar_r * NN + nbase + ar_u * 8;
        CP_ASYNC16(base + VB_AH + ar_r * 80 + ar_u * 16, aThi + ge);
        CP_ASYNC16(base + VB_AL + ar_r * 80 + ar_u * 16, aTlo + ge);
        CP_COMMIT();
    };

    float4 xr[4];
    // ---- prologue ----
    cp_a(0);
    {
        const int nbase = chunk * 1024;
        #pragma unroll
        for (int j = 0; j < 4; j++)
            xr[j] = *(const float4*)&xb[(size_t)(nbase + xr_r + j * 8) * DD + xr_u * 4];
    }

    for (int nc = 0; nc < 32; nc++) {
        char* buf = sm + (nc & 1) * VB_SZ;
        // ---- STS prefetched x ----
        #pragma unroll
        for (int j = 0; j < 4; j++) {
            uint32_t h0, l0, h1, l1;
            split2(make_float2(xr[j].x, xr[j].y), h0, l0);
            split2(make_float2(xr[j].z, xr[j].w), h1, l1);
            int off = (xr_r + j * 8) * 272 + xr_u * 8;
            *(uint2*)(buf + VB_XH + off) = make_uint2(h0, h1);
            *(uint2*)(buf + VB_XL + off) = make_uint2(l0, l1);
        }
        // ---- prefetch next x ----
        if (nc < 31) {
            const int nbase = chunk * 1024 + (nc + 1) * 32;
            #pragma unroll
            for (int j = 0; j < 4; j++)
                xr[j] = *(const float4*)&xb[(size_t)(nbase + xr_r + j * 8) * DD + xr_u * 4];
        }
        CP_WAIT0();
        __syncthreads();
        if (nc < 31) cp_a(nc + 1);

        uint32_t bufo = sb32 + (uint32_t)((nc & 1) * VB_SZ);
        #pragma unroll
        for (int kt = 0; kt < 2; kt++) {
            uint32_t ah[2][4], al[2][4];
            #pragma unroll
            for (int mt = 0; mt < 2; mt++) {
                uint32_t aoff = (uint32_t)((wm * 32 + mt * 16 + (lane & 15)) * 80 +
                                           (kt * 16 + (lane >> 4) * 8) * 2);
                ldsm_x4(ah[mt], bufo + VB_AH + aoff);
                ldsm_x4(al[mt], bufo + VB_AL + aoff);
            }
            uint32_t bh[4][2], bl[4][2];
            #pragma unroll
            for (int p = 0; p < 2; p++) {
                uint32_t t[4];
                uint32_t boff = (uint32_t)((kt * 16 + (lane & 15)) * 272 +
                                           (wn * 32 + p * 16 + (lane >> 4) * 8) * 2);
                ldsm_x4t(t, bufo + VB_XH + boff);
                bh[2*p][0] = t[0]; bh[2*p][1] = t[1];
                bh[2*p+1][0] = t[2]; bh[2*p+1][1] = t[3];
                ldsm_x4t(t, bufo + VB_XL + boff);
                bl[2*p][0] = t[0]; bl[2*p][1] = t[1];
                bl[2*p+1][0] = t[2]; bl[2*p+1][1] = t[3];
            }
            #pragma unroll
            for (int nt = 0; nt < 4; nt++)
                #pragma unroll
                for (int mt = 0; mt < 2; mt++) {
                    mma_bf16(acc[mt][nt], ah[mt], bh[nt]);
                    mma_bf16(acc[mt][nt], ah[mt], bl[nt]);
                    mma_bf16(acc[mt][nt], al[mt], bh[nt]);
                }
        }
    }

    float* vp = g_vpart[chunk] + (size_t)b * KK * DD;
    #pragma unroll
    for (int mt = 0; mt < 2; mt++) {
        int k0 = wm * 32 + mt * 16 + (lane >> 2);
        #pragma unroll
        for (int nt = 0; nt < 4; nt++) {
            int d = d0 + wn * 32 + nt * 8 + (lane & 3) * 2;
            *(float2*)&vp[(size_t)k0 * DD + d]       = make_float2(acc[mt][nt][0], acc[mt][nt][1]);
            *(float2*)&vp[(size_t)(k0 + 8) * DD + d] = make_float2(acc[mt][nt][2], acc[mt][nt][3]);
        }
    }
}

// ---------------------------------------------------------------------------
// Kernel 3: finisher — sum partials, subtract a_sum*clusters2, transpose to
// out[b][d][k], per-(b,k) norm^2.
// ---------------------------------------------------------------------------
__global__ __launch_bounds__(256) void k_fin(float* __restrict__ out)
{
    __shared__ float sT[64][66];
    __shared__ float sN[64];
    const int b = blockIdx.y, dg = blockIdx.x;
    const int lane = threadIdx.x & 31, w = threadIdx.x >> 5;
    const float* vp0 = g_vpart[0] + (size_t)b * KK * DD;
    const float* vp1 = g_vpart[1] + (size_t)b * KK * DD;

    #pragma unroll
    for (int kr = 0; kr < 8; kr++) {
        int k = w * 8 + kr;
        float as = g_asum[b * KK + k];
        int d = dg * 64 + lane;
        float v0 = vp0[(size_t)k * DD + d]      + vp1[(size_t)k * DD + d]
                 - as * g_c2T[k * DD + d];
        float v1 = vp0[(size_t)k * DD + d + 32] + vp1[(size_t)k * DD + d + 32]
                 - as * g_c2T[k * DD + d + 32];
        sT[lane][k]      = v0;
        sT[lane + 32][k] = v1;
        float n2 = v0 * v0 + v1 * v1;
        #pragma unroll
        for (int o = 16; o >= 1; o >>= 1) n2 += __shfl_xor_sync(0xffffffffu, n2, o);
        if (lane == 0) sN[k] = n2;
    }
    __syncthreads();
    if (threadIdx.x < KK)
        atomicAdd(&g_norm2[b * KK + threadIdx.x], sN[threadIdx.x]);
    #pragma unroll
    for (int j = 0; j < 16; j++) {
        int idx = threadIdx.x + j * 256;
        int d = idx >> 6, k = idx & 63;
        out[((size_t)b * DD + dg * 64 + d) * KK + k] = sT[d][k];
    }
}

// ---------------------------------------------------------------------------
// Kernel 4: fused scale compute + in-place output scaling
// ---------------------------------------------------------------------------
__global__ __launch_bounds__(256) void k_out(float* __restrict__ out) {
    __shared__ float sInv[KK];
    __shared__ float sh[2];
    const int b = blockIdx.y, dg = blockIdx.x;
    const int t = threadIdx.x;
    if (t < KK) {
        float n2 = g_norm2[b * KK + t];
        float inv = 1.0f / fmaxf(sqrtf(n2), 1e-12f);
        float c = n2 * inv * inv;
        #pragma unroll
        for (int o = 16; o >= 1; o >>= 1) c += __shfl_xor_sync(0xffffffffu, c, o);
        if ((t & 31) == 0) sh[t >> 5] = c;
        sInv[t] = inv;
    }
    __syncthreads();
    float invt = 1.0f / fmaxf(sqrtf(sh[0] + sh[1]), 1e-12f);
    size_t base = (size_t)b * DD * KK + (size_t)dg * 4096;
    #pragma unroll
    for (int j = 0; j < 16; j++) {
        int i = t + j * 256;
        out[base + i] = out[base + i] * (sInv[i & 63] * invt);
    }
}

// ---------------------------------------------------------------------------
extern "C" void kernel_launch(void* const* d_in, const int* in_sizes, int n_in,
                              void* d_out, int out_size) {
    const float* x         = (const float*)d_in[0];
    const float* clusters  = (const float*)d_in[1];
    const float* clusters2 = (const float*)d_in[2];
    const float* bnw       = (const float*)d_in[3];
    const float* bnb       = (const float*)d_in[4];
    const float* rm        = (const float*)d_in[5];
    const float* rv        = (const float*)d_in[6];
    float* out = (float*)d_out;

    cudaFuncSetAttribute(k_logits_mma, cudaFuncAttributeMaxDynamicSharedMemorySize, L_SMEM);

    k_prep<<<(DD * KGC + 255) / 256, 256>>>(clusters);
    k_prep2<<<KK, DD>>>(clusters2);
    dim3 g1(NN / 128, BB);
    k_logits_mma<<<g1, 256, L_SMEM>>>(x, bnw, bnb, rm, rv);
    dim3 g2(DD / 128, 2, BB);
    k_vlad_mma<<<g2, 256>>>(x);
    dim3 g3(8, BB);
    k_fin<<<g3, 256>>>(out);
    dim3 g4(8, BB);
    k_out<<<g4, 256>>>(out);
}

// round 13
// speedup vs baseline: 1.5820x; 1.0306x over previous
#include <cuda_runtime.h>
#include <cuda_bf16.h>
#include <cstdint>

#define BB 64
#define NN 2048
#define DD 512
#define KK 64
#define KGC 80

// Scratch (device globals — no allocation allowed)
__device__ __align__(16) __nv_bfloat16 g_aThi[(size_t)BB * KK * NN]; // assignT hi [b][k][n]
__device__ __align__(16) __nv_bfloat16 g_aTlo[(size_t)BB * KK * NN]; // assignT lo
__device__ float g_vpart[(size_t)BB * KK * DD];
__device__ float g_asum[BB * KK];
__device__ float g_norm2[BB * KK];
__device__ __align__(16) __nv_bfloat16 g_cHi[DD * KGC];
__device__ __align__(16) __nv_bfloat16 g_cLo[DD * KGC];
__device__ float g_c2T[KK * DD];

// ===================== helpers =====================
__device__ __forceinline__ uint32_t smem_to_u32(const void* p) {
    uint32_t a;
    asm("{ .reg .u64 t; cvta.to.shared.u64 t, %1; cvt.u32.u64 %0, t; }" : "=r"(a) : "l"(p));
    return a;
}
__device__ __forceinline__ void mma_bf16(float* c, const uint32_t* a, const uint32_t* b) {
    asm volatile("mma.sync.aligned.m16n8k16.row.col.f32.bf16.bf16.f32 "
        "{%0,%1,%2,%3}, {%4,%5,%6,%7}, {%8,%9}, {%0,%1,%2,%3};"
        : "+f"(c[0]), "+f"(c[1]), "+f"(c[2]), "+f"(c[3])
        : "r"(a[0]), "r"(a[1]), "r"(a[2]), "r"(a[3]), "r"(b[0]), "r"(b[1]));
}
__device__ __forceinline__ void ldsm_x4(uint32_t* r, uint32_t addr) {
    asm volatile("ldmatrix.sync.aligned.m8n8.x4.shared.b16 {%0,%1,%2,%3}, [%4];"
        : "=r"(r[0]), "=r"(r[1]), "=r"(r[2]), "=r"(r[3]) : "r"(addr));
}
__device__ __forceinline__ void ldsm_x4t(uint32_t* r, uint32_t addr) {
    asm volatile("ldmatrix.sync.aligned.m8n8.x4.trans.shared.b16 {%0,%1,%2,%3}, [%4];"
        : "=r"(r[0]), "=r"(r[1]), "=r"(r[2]), "=r"(r[3]) : "r"(addr));
}
__device__ __forceinline__ void ldsm_x2t(uint32_t* r, uint32_t addr) {
    asm volatile("ldmatrix.sync.aligned.m8n8.x2.trans.shared.b16 {%0,%1}, [%2];"
        : "=r"(r[0]), "=r"(r[1]) : "r"(addr));
}
__device__ __forceinline__ void split2(float2 v, uint32_t& hi, uint32_t& lo) {
    __nv_bfloat162 h = __float22bfloat162_rn(v);
    float2 hf = __bfloat1622float2(h);
    __nv_bfloat162 l = __float22bfloat162_rn(make_float2(v.x - hf.x, v.y - hf.y));
    hi = *(uint32_t*)&h;
    lo = *(uint32_t*)&l;
}
#define CP_ASYNC16(dst, src) \
    asm volatile("cp.async.cg.shared.global [%0], [%1], 16;" :: "r"(dst), "l"(src) : "memory")
#define CP_COMMIT() asm volatile("cp.async.commit_group;" ::: "memory")
#define CP_WAIT0()  asm volatile("cp.async.wait_group 0;" ::: "memory")

// ---------------------------------------------------------------------------
// Kernel P1: split clusters to bf16 hi/lo + zero accumulators
// ---------------------------------------------------------------------------
__global__ void k_prep(const float* __restrict__ clusters) {
    int i = blockIdx.x * 256 + threadIdx.x;
    if (i < DD * KGC) {
        float v = clusters[i];
        __nv_bfloat16 h = __float2bfloat16(v);
        g_cHi[i] = h;
        g_cLo[i] = __float2bfloat16(v - __bfloat162float(h));
    }
    if (i < BB * KK) { g_asum[i] = 0.0f; g_norm2[i] = 0.0f; }
}
// Kernel P2: transpose clusters2 [512][64] -> [64][512]
__global__ void k_prep2(const float* __restrict__ clusters2) {
    int k = blockIdx.x;
    int d = threadIdx.x;
    g_c2T[k * DD + d] = clusters2[d * KK + k];
}

// ---------------------------------------------------------------------------
// Kernel 1: logits GEMM (mma.sync bf16x3) + BN + softmax + a_sum + assignT
// CTA: 256 threads = 8 warps, 4 M-split x 2 N-split. Tile M=128 x N=80,
// K=512 in 16 chunks of 32 d, double-buffered smem, 1 sync/stage.
// A: register prefetch + convert + STS. B: cp.async.cg (bf16 pre-split).
// ---------------------------------------------------------------------------
#define LB_AH 0
#define LB_AL 10240
#define LB_BH 20480
#define LB_BL 26112
#define LB_SZ 31744
#define L_BN  63488      // 240 floats
#define L_AS  64448      // 256 floats
#define L_PM  65472      // 256 floats
#define L_PS  66496      // 256 floats
#define L_SMEM 67520

__global__ __launch_bounds__(256, 2) void k_logits_mma(
    const float* __restrict__ x,
    const float* __restrict__ bnw, const float* __restrict__ bnb,
    const float* __restrict__ rm, const float* __restrict__ rv)
{
    extern __shared__ __align__(16) char smem[];
    const int tid = threadIdx.x;
    const int lane = tid & 31, w = tid >> 5;
    const int wm = w & 3, wn = w >> 2;           // 4 M-warps x 2 N-warps
    const int b = blockIdx.y, n0 = blockIdx.x * 128;
    const float* xb = x + ((size_t)b * NN + n0) * DD;
    uint32_t sb32 = smem_to_u32(smem);

    float* sScale = (float*)(smem + L_BN);
    float* sRm = sScale + 80;
    float* sBb = sScale + 160;
    if (tid < KGC) {
        sScale[tid] = bnw[tid] * rsqrtf(rv[tid] + 1e-5f);
        sRm[tid] = rm[tid];
        sBb[tid] = bnb[tid];
    }

    float acc[2][5][4];
    #pragma unroll
    for (int mt = 0; mt < 2; mt++)
        #pragma unroll
        for (int nt = 0; nt < 5; nt++)
            #pragma unroll
            for (int e = 0; e < 4; e++) acc[mt][nt][e] = 0.f;

    const int xr_r = tid >> 3, xr_u = tid & 7;
    const int br0 = tid / 10, bc0 = tid - br0 * 10;
    const int bidx1 = tid + 256;
    const int u1 = bidx1 >= 320 ? bidx1 - 320 : bidx1;
    const int barr1 = bidx1 >= 320;
    const int br1 = u1 / 10, bc1 = u1 - br1 * 10;
    const int u2 = tid + 512 - 320;
    const int br2 = u2 / 10, bc2 = u2 - br2 * 10;
    const bool bp2 = tid < 128;

    auto cp_b = [&](int stage) {
        uint32_t base = sb32 + (uint32_t)((stage & 1) * LB_SZ);
        const __nv_bfloat16* s0 = g_cHi + (size_t)(stage * 32 + br0) * KGC + bc0 * 8;
        CP_ASYNC16(base + LB_BH + br0 * 176 + bc0 * 16, s0);
        const __nv_bfloat16* s1 = (barr1 ? g_cLo : g_cHi) + (size_t)(stage * 32 + br1) * KGC + bc1 * 8;
        CP_ASYNC16(base + (barr1 ? LB_BL : LB_BH) + br1 * 176 + bc1 * 16, s1);
        if (bp2) {
            const __nv_bfloat16* s2 = g_cLo + (size_t)(stage * 32 + br2) * KGC + bc2 * 8;
            CP_ASYNC16(base + LB_BL + br2 * 176 + bc2 * 16, s2);
        }
        CP_COMMIT();
    };

    float4 xr[4];
    cp_b(0);
    #pragma unroll
    for (int j = 0; j < 4; j++)
        xr[j] = *(const float4*)&xb[(size_t)(xr_r + j * 32) * DD + xr_u * 4];

    for (int dt = 0; dt < 16; dt++) {
        char* buf = smem + (dt & 1) * LB_SZ;
        #pragma unroll
        for (int j = 0; j < 4; j++) {
            uint32_t h0, l0, h1, l1;
            split2(make_float2(xr[j].x, xr[j].y), h0, l0);
            split2(make_float2(xr[j].z, xr[j].w), h1, l1);
            int off = (xr_r + j * 32) * 80 + xr_u * 8;
            *(uint2*)(buf + LB_AH + off) = make_uint2(h0, h1);
            *(uint2*)(buf + LB_AL + off) = make_uint2(l0, l1);
        }
        if (dt < 15) {
            #pragma unroll
            for (int j = 0; j < 4; j++)
                xr[j] = *(const float4*)&xb[(size_t)(xr_r + j * 32) * DD +
                                            (dt + 1) * 32 + xr_u * 4];
        }
        CP_WAIT0();
        __syncthreads();
        if (dt < 15) cp_b(dt + 1);

        uint32_t bufo = sb32 + (uint32_t)((dt & 1) * LB_SZ);
        #pragma unroll
        for (int kt = 0; kt < 2; kt++) {
            uint32_t ah[2][4], al[2][4];
            #pragma unroll
            for (int mt = 0; mt < 2; mt++) {
                uint32_t aoff = (uint32_t)((wm * 32 + mt * 16 + (lane & 15)) * 80 +
                                           (kt * 16 + (lane >> 4) * 8) * 2);
                ldsm_x4(ah[mt], bufo + LB_AH + aoff);
                ldsm_x4(al[mt], bufo + LB_AL + aoff);
            }
            uint32_t bh[5][2], bl[5][2];
            #pragma unroll
            for (int p = 0; p < 2; p++) {
                uint32_t t[4];
                uint32_t boff = (uint32_t)((kt * 16 + (lane & 15)) * 176 +
                                           (wn * 40 + p * 16 + (lane >> 4) * 8) * 2);
                ldsm_x4t(t, bufo + LB_BH + boff);
                bh[2*p][0] = t[0]; bh[2*p][1] = t[1];
                bh[2*p+1][0] = t[2]; bh[2*p+1][1] = t[3];
                ldsm_x4t(t, bufo + LB_BL + boff);
                bl[2*p][0] = t[0]; bl[2*p][1] = t[1];
                bl[2*p+1][0] = t[2]; bl[2*p+1][1] = t[3];
            }
            {
                uint32_t boff = (uint32_t)((kt * 16 + (lane & 15)) * 176 + (wn * 40 + 32) * 2);
                ldsm_x2t(bh[4], bufo + LB_BH + boff);
                ldsm_x2t(bl[4], bufo + LB_BL + boff);
            }
            #pragma unroll
            for (int nt = 0; nt < 5; nt++)
                #pragma unroll
                for (int mt = 0; mt < 2; mt++) {
                    mma_bf16(acc[mt][nt], ah[mt], bh[nt]);
                    mma_bf16(acc[mt][nt], ah[mt], bl[nt]);
                    mma_bf16(acc[mt][nt], al[mt], bh[nt]);
                }
        }
    }
    __syncthreads();

    // ---- BN affine ----
    #pragma unroll
    for (int nt = 0; nt < 5; nt++) {
        int c0 = wn * 40 + nt * 8 + (lane & 3) * 2;
        float s0 = sScale[c0], s1 = sScale[c0 + 1];
        float m0 = sRm[c0],    m1 = sRm[c0 + 1];
        float q0 = sBb[c0],    q1 = sBb[c0 + 1];
        #pragma unroll
        for (int mt = 0; mt < 2; mt++) {
            acc[mt][nt][0] = (acc[mt][nt][0] - m0) * s0 + q0;
            acc[mt][nt][1] = (acc[mt][nt][1] - m1) * s1 + q1;
            acc[mt][nt][2] = (acc[mt][nt][2] - m0) * s0 + q0;
            acc[mt][nt][3] = (acc[mt][nt][3] - m1) * s1 + q1;
        }
    }

    // ---- softmax: 2-pass smem reduction across N-warps ----
    float* sPM = (float*)(smem + L_PM);
    float* sPS = (float*)(smem + L_PS);
    float* sOut = (float*)smem;                  // [128][66] floats

    #pragma unroll
    for (int h = 0; h < 4; h++) {
        int mt = h >> 1, hh = h & 1;
        float mx = -3.4e38f;
        #pragma unroll
        for (int nt = 0; nt < 5; nt++)
            mx = fmaxf(mx, fmaxf(acc[mt][nt][hh * 2], acc[mt][nt][hh * 2 + 1]));
        mx = fmaxf(mx, __shfl_xor_sync(0xffffffffu, mx, 1));
        mx = fmaxf(mx, __shfl_xor_sync(0xffffffffu, mx, 2));
        int row = wm * 32 + mt * 16 + hh * 8 + (lane >> 2);
        if ((lane & 3) == 0) sPM[row * 2 + wn] = mx;
    }
    __syncthreads();
    #pragma unroll
    for (int h = 0; h < 4; h++) {
        int mt = h >> 1, hh = h & 1;
        int row = wm * 32 + mt * 16 + hh * 8 + (lane >> 2);
        float m = fmaxf(sPM[row * 2], sPM[row * 2 + 1]);
        float sum = 0.f;
        #pragma unroll
        for (int nt = 0; nt < 5; nt++) {
            float e0 = __expf(acc[mt][nt][hh * 2] - m);
            float e1 = __expf(acc[mt][nt][hh * 2 + 1] - m);
            acc[mt][nt][hh * 2] = e0;
            acc[mt][nt][hh * 2 + 1] = e1;
            sum += e0 + e1;
        }
        sum += __shfl_xor_sync(0xffffffffu, sum, 1);
        sum += __shfl_xor_sync(0xffffffffu, sum, 2);
        if ((lane & 3) == 0) sPS[row * 2 + wn] = sum;
    }
    __syncthreads();
    const int ntmax = wn ? 3 : 5;
    #pragma unroll
    for (int h = 0; h < 4; h++) {
        int mt = h >> 1, hh = h & 1;
        int row = wm * 32 + mt * 16 + hh * 8 + (lane >> 2);
        float inv = 1.0f / (sPS[row * 2] + sPS[row * 2 + 1]);
        #pragma unroll
        for (int nt = 0; nt < 5; nt++) {
            if (nt < ntmax) {
                int col = wn * 40 + nt * 8 + (lane & 3) * 2;
                float2 v = make_float2(acc[mt][nt][hh * 2] * inv,
                                       acc[mt][nt][hh * 2 + 1] * inv);
                *(float2*)&sOut[row * 66 + col] = v;
            }
        }
    }
    __syncthreads();

    // ---- a_sum ----
    float* sAs = (float*)(smem + L_AS);
    {
        int k = tid & 63, qq = tid >> 6;
        float s = 0.f;
        #pragma unroll 8
        for (int r = qq * 32; r < qq * 32 + 32; r++) s += sOut[r * 66 + k];
        sAs[qq * 64 + k] = s;
    }
    __syncthreads();
    if (tid < KK)
        atomicAdd(&g_asum[b * KK + tid],
                  sAs[tid] + sAs[64 + tid] + sAs[128 + tid] + sAs[192 + tid]);

    // ---- assignment^T bf16 hi/lo, packed bf16x2 stores (2 n per thread) ----
    {
        int np = (tid & 63) * 2;          // n-pair base
        int kh = (tid >> 6) * 16;         // 16 k per quarter
        uint32_t* aThi = (uint32_t*)(g_aThi + (size_t)b * KK * NN + n0 + np);
        uint32_t* aTlo = (uint32_t*)(g_aTlo + (size_t)b * KK * NN + n0 + np);
        #pragma unroll 4
        for (int kk2 = 0; kk2 < 16; kk2++) {
            int k = kh + kk2;
            float v0 = sOut[np * 66 + k];
            float v1 = sOut[(np + 1) * 66 + k];
            uint32_t hi, lo;
            split2(make_float2(v0, v1), hi, lo);
            aThi[(size_t)k * (NN / 2)] = hi;
            aTlo[(size_t)k * (NN / 2)] = lo;
        }
    }
}

// ---------------------------------------------------------------------------
// Kernel 2: vlad GEMM (mma.sync bf16x3): D[k_clu][d] = assign^T @ x
// CTA: 256 threads (2 M x 4 N warps), tile M=64 x N=128 d, FULL K(n)=2048
// in 64 stages. x: register prefetch + STS. aT: cp.async. Double-buffered.
// Grid (4 dtiles, B) = 256 CTAs. Writes final sums to g_vpart.
// ---------------------------------------------------------------------------
#define VB_XH 0
#define VB_XL 8704
#define VB_AH 17408
#define VB_AL 22528
#define VB_SZ 27648

__global__ __launch_bounds__(256, 2) void k_vlad_mma(const float* __restrict__ x)
{
    __shared__ __align__(16) char sm[2 * VB_SZ];
    const int tid = threadIdx.x, lane = tid & 31, w = tid >> 5;
    const int wm = w & 1, wn = w >> 1;
    const int b = blockIdx.y, d0 = blockIdx.x * 128;
    const float* xb = x + (size_t)b * NN * DD + d0;
    const __nv_bfloat16* aThi = g_aThi + (size_t)b * KK * NN;
    const __nv_bfloat16* aTlo = g_aTlo + (size_t)b * KK * NN;
    uint32_t sb32 = smem_to_u32(sm);

    float acc[2][4][4];
    #pragma unroll
    for (int mt = 0; mt < 2; mt++)
        #pragma unroll
        for (int nt = 0; nt < 4; nt++)
            #pragma unroll
            for (int e = 0; e < 4; e++) acc[mt][nt][e] = 0.f;

    const int xr_r = tid >> 5, xr_u = tid & 31;
    const int ar_r = tid >> 2, ar_u = tid & 3;

    auto cp_a = [&](int nc) {
        const int nbase = nc * 32;
        uint32_t base = sb32 + (uint32_t)((nc & 1) * VB_SZ);
        size_t ge = (size_t)ar_r * NN + nbase + ar_u * 8;
        CP_ASYNC16(base + VB_AH + ar_r * 80 + ar_u * 16, aThi + ge);
        CP_ASYNC16(base + VB_AL + ar_r * 80 + ar_u * 16, aTlo + ge);
        CP_COMMIT();
    };

    float4 xr[4];
    cp_a(0);
    #pragma unroll
    for (int j = 0; j < 4; j++)
        xr[j] = *(const float4*)&xb[(size_t)(xr_r + j * 8) * DD + xr_u * 4];

    for (int nc = 0; nc < 64; nc++) {
        char* buf = sm + (nc & 1) * VB_SZ;
        #pragma unroll
        for (int j = 0; j < 4; j++) {
            uint32_t h0, l0, h1, l1;
            split2(make_float2(xr[j].x, xr[j].y), h0, l0);
            split2(make_float2(xr[j].z, xr[j].w), h1, l1);
            int off = (xr_r + j * 8) * 272 + xr_u * 8;
            *(uint2*)(buf + VB_XH + off) = make_uint2(h0, h1);
            *(uint2*)(buf + VB_XL + off) = make_uint2(l0, l1);
        }
        if (nc < 63) {
            const int nbase = (nc + 1) * 32;
            #pragma unroll
            for (int j = 0; j < 4; j++)
                xr[j] = *(const float4*)&xb[(size_t)(nbase + xr_r + j * 8) * DD + xr_u * 4];
        }
        CP_WAIT0();
        __syncthreads();
        if (nc < 63) cp_a(nc + 1);

        uint32_t bufo = sb32 + (uint32_t)((nc & 1) * VB_SZ);
        #pragma unroll
        for (int kt = 0; kt < 2; kt++) {
            uint32_t ah[2][4], al[2][4];
            #pragma unroll
            for (int mt = 0; mt < 2; mt++) {
                uint32_t aoff = (uint32_t)((wm * 32 + mt * 16 + (lane & 15)) * 80 +
                                           (kt * 16 + (lane >> 4) * 8) * 2);
                ldsm_x4(ah[mt], bufo + VB_AH + aoff);
                ldsm_x4(al[mt], bufo + VB_AL + aoff);
            }
            uint32_t bh[4][2], bl[4][2];
            #pragma unroll
            for (int p = 0; p < 2; p++) {
                uint32_t t[4];
                uint32_t boff = (uint32_t)((kt * 16 + (lane & 15)) * 272 +
                                           (wn * 32 + p * 16 + (lane >> 4) * 8) * 2);
                ldsm_x4t(t, bufo + VB_XH + boff);
                bh[2*p][0] = t[0]; bh[2*p][1] = t[1];
                bh[2*p+1][0] = t[2]; bh[2*p+1][1] = t[3];
                ldsm_x4t(t, bufo + VB_XL + boff);
                bl[2*p][0] = t[0]; bl[2*p][1] = t[1];
                bl[2*p+1][0] = t[2]; bl[2*p+1][1] = t[3];
            }
            #pragma unroll
            for (int nt = 0; nt < 4; nt++)
                #pragma unroll
                for (int mt = 0; mt < 2; mt++) {
                    mma_bf16(acc[mt][nt], ah[mt], bh[nt]);
                    mma_bf16(acc[mt][nt], ah[mt], bl[nt]);
                    mma_bf16(acc[mt][nt], al[mt], bh[nt]);
                }
        }
    }

    float* vp = g_vpart + (size_t)b * KK * DD;
    #pragma unroll
    for (int mt = 0; mt < 2; mt++) {
        int k0 = wm * 32 + mt * 16 + (lane >> 2);
        #pragma unroll
        for (int nt = 0; nt < 4; nt++) {
            int d = d0 + wn * 32 + nt * 8 + (lane & 3) * 2;
            *(float2*)&vp[(size_t)k0 * DD + d]       = make_float2(acc[mt][nt][0], acc[mt][nt][1]);
            *(float2*)&vp[(size_t)(k0 + 8) * DD + d] = make_float2(acc[mt][nt][2], acc[mt][nt][3]);
        }
    }
}

// ---------------------------------------------------------------------------
// Kernel 3: finisher — subtract a_sum*clusters2, transpose to out[b][d][k],
// per-(b,k) norm^2.
// ---------------------------------------------------------------------------
__global__ __launch_bounds__(256) void k_fin(float* __restrict__ out)
{
    __shared__ float sT[64][66];
    __shared__ float sN[64];
    const int b = blockIdx.y, dg = blockIdx.x;
    const int lane = threadIdx.x & 31, w = threadIdx.x >> 5;
    const float* vp = g_vpart + (size_t)b * KK * DD;

    #pragma unroll
    for (int kr = 0; kr < 8; kr++) {
        int k = w * 8 + kr;
        float as = g_asum[b * KK + k];
        int d = dg * 64 + lane;
        float v0 = vp[(size_t)k * DD + d]      - as * g_c2T[k * DD + d];
        float v1 = vp[(size_t)k * DD + d + 32] - as * g_c2T[k * DD + d + 32];
        sT[lane][k]      = v0;
        sT[lane + 32][k] = v1;
        float n2 = v0 * v0 + v1 * v1;
        #pragma unroll
        for (int o = 16; o >= 1; o >>= 1) n2 += __shfl_xor_sync(0xffffffffu, n2, o);
        if (lane == 0) sN[k] = n2;
    }
    __syncthreads();
    if (threadIdx.x < KK)
        atomicAdd(&g_norm2[b * KK + threadIdx.x], sN[threadIdx.x]);
    #pragma unroll
    for (int j = 0; j < 16; j++) {
        int idx = threadIdx.x + j * 256;
        int d = idx >> 6, k = idx & 63;
        out[((size_t)b * DD + dg * 64 + d) * KK + k] = sT[d][k];
    }
}

// ---------------------------------------------------------------------------
// Kernel 4: fused scale compute + in-place output scaling
// ---------------------------------------------------------------------------
__global__ __launch_bounds__(256) void k_out(float* __restrict__ out) {
    __shared__ float sInv[KK];
    __shared__ float sh[2];
    const int b = blockIdx.y, dg = blockIdx.x;
    const int t = threadIdx.x;
    if (t < KK) {
        float n2 = g_norm2[b * KK + t];
        float inv = 1.0f / fmaxf(sqrtf(n2), 1e-12f);
        float c = n2 * inv * inv;
        #pragma unroll
        for (int o = 16; o >= 1; o >>= 1) c += __shfl_xor_sync(0xffffffffu, c, o);
        if ((t & 31) == 0) sh[t >> 5] = c;
        sInv[t] = inv;
    }
    __syncthreads();
    float invt = 1.0f / fmaxf(sqrtf(sh[0] + sh[1]), 1e-12f);
    size_t base = (size_t)b * DD * KK + (size_t)dg * 4096;
    #pragma unroll
    for (int j = 0; j < 16; j++) {
        int i = t + j * 256;
        out[base + i] = out[base + i] * (sInv[i & 63] * invt);
    }
}

// ---------------------------------------------------------------------------
extern "C" void kernel_launch(void* const* d_in, const int* in_sizes, int n_in,
                              void* d_out, int out_size) {
    const float* x         = (const float*)d_in[0];
    const float* clusters  = (const float*)d_in[1];
    const float* clusters2 = (const float*)d_in[2];
    const float* bnw       = (const float*)d_in[3];
    const float* bnb       = (const float*)d_in[4];
    const float* rm        = (const float*)d_in[5];
    const float* rv        = (const float*)d_in[6];
    float* out = (float*)d_out;

    cudaFuncSetAttribute(k_logits_mma, cudaFuncAttributeMaxDynamicSharedMemorySize, L_SMEM);

    k_prep<<<(DD * KGC + 255) / 256, 256>>>(clusters);
    k_prep2<<<KK, DD>>>(clusters2);
    dim3 g1(NN / 128, BB);
    k_logits_mma<<<g1, 256, L_SMEM>>>(x, bnw, bnb, rm, rv);
    dim3 g2(DD / 128, BB);
    k_vlad_mma<<<g2, 256>>>(x);
    dim3 g3(8, BB);
    k_fin<<<g3, 256>>>(out);
    dim3 g4(8, BB);
    k_out<<<g4, 256>>>(out);
}